// round 16
// baseline (speedup 1.0000x reference)
#include <cuda_runtime.h>
#include <cuda_bf16.h>
#include <math.h>
#include <stdint.h>

#define B_  8
#define LQ_ 1024
#define LK_ 1024
#define D_  1024
#define H_  16
#define HD_ 64
#define NTOK (B_ * LQ_)
#define NELEM ((size_t)B_ * LQ_ * D_)
#define NW (D_ * D_)

// Scratch (static device globals)
__device__ float g_Q[NELEM];
__device__ float g_K[NELEM];
__device__ float g_V[NELEM];
__device__ float g_G[NELEM];
__device__ float g_O[NELEM];
// int8 quantized activations: slot 0=query(->gated O reuse), 1=key, 2=value
__device__ int8_t g_A8h[3 * NELEM];
__device__ int8_t g_A8l[3 * NELEM];
__device__ float  g_SA[3 * NTOK];
// int8 quantized weights: slots 0..4 = Wq, Wg, Wk, Wv, Wo
__device__ int8_t g_W8h[5 * NW];
__device__ int8_t g_W8l[5 * NW];
__device__ float  g_SW[5 * D_];
// head-major [B,H,L,HD] bf16 hi/lo for attention
__device__ __nv_bfloat16 g_Qh[NELEM];
__device__ __nv_bfloat16 g_Ql[NELEM];
__device__ __nv_bfloat16 g_Kh[NELEM];
__device__ __nv_bfloat16 g_Kl[NELEM];
__device__ __nv_bfloat16 g_Vh[NELEM];
__device__ __nv_bfloat16 g_Vl[NELEM];

// ---------------------------------------------------------------------------
// PTX helpers
// ---------------------------------------------------------------------------
__device__ __forceinline__ void ldsm_x4(unsigned* r, unsigned addr) {
    asm volatile("ldmatrix.sync.aligned.m8n8.x4.shared.b16 {%0,%1,%2,%3}, [%4];\n"
                 : "=r"(r[0]), "=r"(r[1]), "=r"(r[2]), "=r"(r[3]) : "r"(addr));
}
__device__ __forceinline__ void ldsm_x4_t(unsigned* r, unsigned addr) {
    asm volatile("ldmatrix.sync.aligned.m8n8.x4.trans.shared.b16 {%0,%1,%2,%3}, [%4];\n"
                 : "=r"(r[0]), "=r"(r[1]), "=r"(r[2]), "=r"(r[3]) : "r"(addr));
}
__device__ __forceinline__ void mma_bf16(float* c, const unsigned* a, const unsigned* b) {
    asm volatile(
        "mma.sync.aligned.m16n8k16.row.col.f32.bf16.bf16.f32 "
        "{%0,%1,%2,%3}, {%4,%5,%6,%7}, {%8,%9}, {%0,%1,%2,%3};\n"
        : "+f"(c[0]), "+f"(c[1]), "+f"(c[2]), "+f"(c[3])
        : "r"(a[0]), "r"(a[1]), "r"(a[2]), "r"(a[3]), "r"(b[0]), "r"(b[1]));
}
__device__ __forceinline__ void mma_s8(int* c, const unsigned* a, const unsigned* b) {
    asm volatile(
        "mma.sync.aligned.m16n8k32.row.col.s32.s8.s8.s32 "
        "{%0,%1,%2,%3}, {%4,%5,%6,%7}, {%8,%9}, {%0,%1,%2,%3};\n"
        : "+r"(c[0]), "+r"(c[1]), "+r"(c[2]), "+r"(c[3])
        : "r"(a[0]), "r"(a[1]), "r"(a[2]), "r"(a[3]), "r"(b[0]), "r"(b[1]));
}
__device__ __forceinline__ unsigned smaddr(const void* p) {
    return (unsigned)__cvta_generic_to_shared(p);
}
__device__ __forceinline__ void cp_async16(unsigned dst, const void* src) {
    asm volatile("cp.async.cg.shared.global [%0], [%1], 16;\n"
                 :: "r"(dst), "l"(src));
}
__device__ __forceinline__ void cp_commit() {
    asm volatile("cp.async.commit_group;\n");
}
template <int N>
__device__ __forceinline__ void cp_wait() {
    asm volatile("cp.async.wait_group %0;\n" :: "n"(N));
}

// ---------------------------------------------------------------------------
// Row quantization: x ~= S*(hi*128 + lo), S = max|row|/16256. One block/row.
// ---------------------------------------------------------------------------
__device__ __forceinline__ void quant_row_body(
    const float* __restrict__ x, const float* __restrict__ gate,
    int8_t* __restrict__ hi, int8_t* __restrict__ lo, float* __restrict__ scale)
{
    __shared__ float wmax[8];
    int i0 = threadIdx.x * 4;
    float4 xv = *reinterpret_cast<const float4*>(x + i0);
    float v[4] = {xv.x, xv.y, xv.z, xv.w};
    if (gate) {
        float4 gv = *reinterpret_cast<const float4*>(gate + i0);
        v[0] *= gv.x; v[1] *= gv.y; v[2] *= gv.z; v[3] *= gv.w;
    }
    float m = fmaxf(fmaxf(fabsf(v[0]), fabsf(v[1])), fmaxf(fabsf(v[2]), fabsf(v[3])));
#pragma unroll
    for (int off = 16; off; off >>= 1)
        m = fmaxf(m, __shfl_xor_sync(0xffffffffu, m, off));
    if ((threadIdx.x & 31) == 0) wmax[threadIdx.x >> 5] = m;
    __syncthreads();
    float mm = wmax[0];
#pragma unroll
    for (int j = 1; j < 8; j++) mm = fmaxf(mm, wmax[j]);

    float inv = (mm > 0.0f) ? 16256.0f / mm : 0.0f;
    char h4[4], l4[4];
#pragma unroll
    for (int j = 0; j < 4; j++) {
        int q = (int)rintf(v[j] * inv);
        int ih = (q + 64) >> 7;
        int il = q - (ih << 7);
        h4[j] = (char)ih; l4[j] = (char)il;
    }
    *reinterpret_cast<char4*>(hi + i0) = *reinterpret_cast<char4*>(h4);
    *reinterpret_cast<char4*>(lo + i0) = *reinterpret_cast<char4*>(l4);
    if (threadIdx.x == 0) *scale = (mm > 0.0f) ? mm / 16256.0f : 1.0f;
}

__global__ void quant_w_all_kernel(const float* __restrict__ W0,
                                   const float* __restrict__ W1,
                                   const float* __restrict__ W2,
                                   const float* __restrict__ W3,
                                   const float* __restrict__ W4,
                                   int8_t* __restrict__ hi, int8_t* __restrict__ lo,
                                   float* __restrict__ scale)
{
    int m = blockIdx.x >> 10;
    int r = blockIdx.x & 1023;
    const float* W = (m == 0) ? W0 : (m == 1) ? W1 : (m == 2) ? W2
                   : (m == 3) ? W3 : W4;
    quant_row_body(W + (size_t)r * 1024, nullptr,
                   hi + (size_t)m * NW + (size_t)r * 1024,
                   lo + (size_t)m * NW + (size_t)r * 1024,
                   scale + m * D_ + r);
}

__global__ void quant_act3_kernel(const float* __restrict__ X0,
                                  const float* __restrict__ X1,
                                  const float* __restrict__ X2,
                                  int8_t* __restrict__ hi, int8_t* __restrict__ lo,
                                  float* __restrict__ scale)
{
    int m = blockIdx.x >> 13;
    int r = blockIdx.x & 8191;
    const float* X = (m == 0) ? X0 : (m == 1) ? X1 : X2;
    quant_row_body(X + (size_t)r * 1024, nullptr,
                   hi + (size_t)m * NELEM + (size_t)r * 1024,
                   lo + (size_t)m * NELEM + (size_t)r * 1024,
                   scale + m * NTOK + r);
}

__global__ void quant_gate_kernel(const float* __restrict__ O,
                                  const float* __restrict__ G,
                                  int8_t* __restrict__ hi, int8_t* __restrict__ lo,
                                  float* __restrict__ scale)
{
    int r = blockIdx.x;
    quant_row_body(O + (size_t)r * 1024, G + (size_t)r * 1024,
                   hi + (size_t)r * 1024, lo + (size_t)r * 1024, scale + r);
}

// ---------------------------------------------------------------------------
// int8 hi/lo GEMM, m16n8k32.s8, exact s32 accumulate.
// C[n][m] = Sa[n]*Sw[m]*(16384*hh + 128*mid) + bias[m]
// BM=BN=128, K-block = 64 s8 (64B/row). 256 thr, 8 warps 2(m)x4(n), 64x32 tile.
// 2-stage cp.async pipeline, single __syncthreads per k-block (R15 pattern).
// ---------------------------------------------------------------------------
#define QLDA 80                       // bytes per smem row (64 data + 16 pad)
#define QBUF (128 * QLDA)             // 10240 B per buffer
#define QSMEM (2 * 4 * QBUF)          // 81920 B

__global__ __launch_bounds__(256) void gemm_s8_kernel(
    const int8_t* __restrict__ Ah, const int8_t* __restrict__ Al,
    const int8_t* __restrict__ Wh, const int8_t* __restrict__ Wl,
    const float* __restrict__ Sa, const float* __restrict__ Sw,
    const float* __restrict__ bias, float* __restrict__ C, int act)
{
    extern __shared__ char smq[];

    const int tid = threadIdx.x;
    const int wid = tid >> 5, lane = tid & 31;
    const int bm = blockIdx.y * 128, bn = blockIdx.x * 128;
    const int wm = (wid >> 2) * 64, wn = (wid & 3) * 32;

    const int cr = tid >> 1;          // row 0..127
    const int ccb = (tid & 1) * 32;   // byte col 0 or 32 in 64B chunk

    int acc_hh[4][4][4], acc_mid[4][4][4];
#pragma unroll
    for (int a = 0; a < 4; a++)
#pragma unroll
        for (int b = 0; b < 4; b++)
#pragma unroll
            for (int c = 0; c < 4; c++) { acc_hh[a][b][c] = 0; acc_mid[a][b][c] = 0; }

    auto copy_stage = [&](int s, int kb) {
        char* base = smq + (size_t)s * 4 * QBUF;
        unsigned d = smaddr(base + cr * QLDA + ccb);
        const size_t ga = (size_t)(bm + cr) * 1024 + kb * 64 + ccb;
        const size_t gw = (size_t)(bn + cr) * 1024 + kb * 64 + ccb;
        cp_async16(d,                &Ah[ga]);
        cp_async16(d + 16,           &Ah[ga + 16]);
        cp_async16(d + QBUF,         &Al[ga]);
        cp_async16(d + QBUF + 16,    &Al[ga + 16]);
        cp_async16(d + 2 * QBUF,     &Wh[gw]);
        cp_async16(d + 2 * QBUF + 16,&Wh[gw + 16]);
        cp_async16(d + 3 * QBUF,     &Wl[gw]);
        cp_async16(d + 3 * QBUF + 16,&Wl[gw + 16]);
    };

    copy_stage(0, 0);
    cp_commit();

    const int NKB = 16;               // 1024 / 64
    for (int kb = 0; kb < NKB; kb++) {
        cp_wait<0>();
        __syncthreads();
        if (kb + 1 < NKB) {
            copy_stage((kb + 1) & 1, kb + 1);
            cp_commit();
        }

        {
            const char* bAh = smq + (size_t)(kb & 1) * 4 * QBUF;
            const char* bAl = bAh + QBUF;
            const char* bWh = bAh + 2 * QBUF;
            const char* bWl = bAh + 3 * QBUF;
#pragma unroll
            for (int kkb = 0; kkb < 64; kkb += 32) {   // two k32 sub-blocks
                unsigned ah[4][4], al[4][4], bh[2][4], bl[2][4];
#pragma unroll
                for (int mt = 0; mt < 4; mt++) {
                    int row = wm + mt * 16 + (lane & 15);
                    int colb = kkb + (lane >> 4) * 16;
                    ldsm_x4(ah[mt], smaddr(bAh + row * QLDA + colb));
                    ldsm_x4(al[mt], smaddr(bAl + row * QLDA + colb));
                }
#pragma unroll
                for (int p = 0; p < 2; p++) {
                    int row = wn + p * 16 + ((lane >> 4) & 1) * 8 + (lane & 7);
                    int colb = kkb + ((lane >> 3) & 1) * 16;
                    ldsm_x4(bh[p], smaddr(bWh + row * QLDA + colb));
                    ldsm_x4(bl[p], smaddr(bWl + row * QLDA + colb));
                }
#pragma unroll
                for (int mt = 0; mt < 4; mt++) {
#pragma unroll
                    for (int nt = 0; nt < 4; nt++) {
                        unsigned bhf[2] = { bh[nt >> 1][(nt & 1) * 2],
                                            bh[nt >> 1][(nt & 1) * 2 + 1] };
                        unsigned blf[2] = { bl[nt >> 1][(nt & 1) * 2],
                                            bl[nt >> 1][(nt & 1) * 2 + 1] };
                        mma_s8(acc_hh[mt][nt],  ah[mt], bhf);
                        mma_s8(acc_mid[mt][nt], ah[mt], blf);
                        mma_s8(acc_mid[mt][nt], al[mt], bhf);
                    }
                }
            }
        }
    }

    const int g = lane >> 2, t = lane & 3;
#pragma unroll
    for (int mt = 0; mt < 4; mt++) {
        int row = bm + wm + mt * 16 + g;
        float sa0 = Sa[row], sa1 = Sa[row + 8];
#pragma unroll
        for (int nt = 0; nt < 4; nt++) {
            int col = bn + wn + nt * 8 + t * 2;
            float sw0 = Sw[col], sw1 = Sw[col + 1];
            float b0 = bias[col], b1 = bias[col + 1];
            float c0 = sa0 * sw0 * (16384.0f * (float)acc_hh[mt][nt][0]
                                    + 128.0f * (float)acc_mid[mt][nt][0]) + b0;
            float c1 = sa0 * sw1 * (16384.0f * (float)acc_hh[mt][nt][1]
                                    + 128.0f * (float)acc_mid[mt][nt][1]) + b1;
            float c2 = sa1 * sw0 * (16384.0f * (float)acc_hh[mt][nt][2]
                                    + 128.0f * (float)acc_mid[mt][nt][2]) + b0;
            float c3 = sa1 * sw1 * (16384.0f * (float)acc_hh[mt][nt][3]
                                    + 128.0f * (float)acc_mid[mt][nt][3]) + b1;
            if (act) {
                c0 = 1.0f / (1.0f + __expf(-c0));
                c1 = 1.0f / (1.0f + __expf(-c1));
                c2 = 1.0f / (1.0f + __expf(-c2));
                c3 = 1.0f / (1.0f + __expf(-c3));
            }
            *reinterpret_cast<float2*>(&C[(size_t)row * 1024 + col]) = make_float2(c0, c1);
            *reinterpret_cast<float2*>(&C[(size_t)(row + 8) * 1024 + col]) = make_float2(c2, c3);
        }
    }
}

// ---------------------------------------------------------------------------
// Fused RoPE + split + transpose; Q and K in one launch.
// ---------------------------------------------------------------------------
__global__ void qk_prep2_kernel(const float* __restrict__ Qsrc,
                                const float* __restrict__ Ksrc,
                                const float* __restrict__ cosb,
                                const float* __restrict__ sinb,
                                __nv_bfloat16* __restrict__ Qhi,
                                __nv_bfloat16* __restrict__ Qlo,
                                __nv_bfloat16* __restrict__ Khi,
                                __nv_bfloat16* __restrict__ Klo)
{
    const float* X = blockIdx.y ? Ksrc : Qsrc;
    __nv_bfloat16* hi = blockIdx.y ? Khi : Qhi;
    __nv_bfloat16* lo = blockIdx.y ? Klo : Qlo;

    int bl = blockIdx.x;
    int b = bl >> 10, l = bl & 1023;
    int h = threadIdx.x >> 4, j = threadIdx.x & 15;
    int d0 = j * 2;

    size_t ibase = (size_t)bl * D_ + h * HD_;
    size_t obase = ((size_t)(b * H_ + h) * LK_ + l) * HD_;
    size_t cbase = (size_t)bl * HD_;

    float x0 = X[ibase + d0],      x1 = X[ibase + d0 + 1];
    float y0 = X[ibase + d0 + 32], y1 = X[ibase + d0 + 33];
    float cA0 = cosb[cbase + d0],      sA0 = sinb[cbase + d0];
    float cA1 = cosb[cbase + d0 + 1],  sA1 = sinb[cbase + d0 + 1];
    float cB0 = cosb[cbase + d0 + 32], sB0 = sinb[cbase + d0 + 32];
    float cB1 = cosb[cbase + d0 + 33], sB1 = sinb[cbase + d0 + 33];

    float r0 = x0 * cA0 - y0 * sA0;
    float r1 = x1 * cA1 - y1 * sA1;
    float r2 = y0 * cB0 + x0 * sB0;
    float r3 = y1 * cB1 + x1 * sB1;

    __nv_bfloat16 h0 = __float2bfloat16_rn(r0), h1 = __float2bfloat16_rn(r1);
    __nv_bfloat16 h2 = __float2bfloat16_rn(r2), h3 = __float2bfloat16_rn(r3);
    __nv_bfloat162 hp0; hp0.x = h0; hp0.y = h1;
    __nv_bfloat162 hp1; hp1.x = h2; hp1.y = h3;
    __nv_bfloat162 lp0;
    lp0.x = __float2bfloat16_rn(r0 - __bfloat162float(h0));
    lp0.y = __float2bfloat16_rn(r1 - __bfloat162float(h1));
    __nv_bfloat162 lp1;
    lp1.x = __float2bfloat16_rn(r2 - __bfloat162float(h2));
    lp1.y = __float2bfloat16_rn(r3 - __bfloat162float(h3));

    *reinterpret_cast<__nv_bfloat162*>(&hi[obase + d0]) = hp0;
    *reinterpret_cast<__nv_bfloat162*>(&hi[obase + d0 + 32]) = hp1;
    *reinterpret_cast<__nv_bfloat162*>(&lo[obase + d0]) = lp0;
    *reinterpret_cast<__nv_bfloat162*>(&lo[obase + d0 + 32]) = lp1;
}

__global__ void v_prep_kernel(const float* __restrict__ X,
                              __nv_bfloat16* __restrict__ hi,
                              __nv_bfloat16* __restrict__ lo)
{
    int bl = blockIdx.x;
    int b = bl >> 10, l = bl & 1023;
    int h = threadIdx.x >> 4, j = threadIdx.x & 15;
    int d0 = j * 4;

    size_t ibase = (size_t)bl * D_ + h * HD_ + d0;
    size_t obase = ((size_t)(b * H_ + h) * LK_ + l) * HD_ + d0;

    float4 v = *reinterpret_cast<const float4*>(&X[ibase]);
    float vv[4] = {v.x, v.y, v.z, v.w};
    __nv_bfloat16 hh[4], ll[4];
#pragma unroll
    for (int i = 0; i < 4; i++) {
        hh[i] = __float2bfloat16_rn(vv[i]);
        ll[i] = __float2bfloat16_rn(vv[i] - __bfloat162float(hh[i]));
    }
    *reinterpret_cast<uint2*>(&hi[obase]) = *reinterpret_cast<uint2*>(hh);
    *reinterpret_cast<uint2*>(&lo[obase]) = *reinterpret_cast<uint2*>(ll);
}

// ---------------------------------------------------------------------------
// Tensor-core flash attention (bf16x3), unchanged (passing since R5).
// ---------------------------------------------------------------------------
#define AP 72
#define ATTN_SMEM (6 * 64 * AP * 2 + 64 * 4)

__global__ __launch_bounds__(128) void attn_mma_kernel(
    const __nv_bfloat16* __restrict__ Qh, const __nv_bfloat16* __restrict__ Ql,
    const __nv_bfloat16* __restrict__ Kh, const __nv_bfloat16* __restrict__ Kl,
    const __nv_bfloat16* __restrict__ Vh, const __nv_bfloat16* __restrict__ Vl,
    const unsigned char* __restrict__ mask, float* __restrict__ O)
{
    extern __shared__ char smraw[];
    __nv_bfloat16* sQh = reinterpret_cast<__nv_bfloat16*>(smraw);
    __nv_bfloat16* sQl = sQh + 64 * AP;
    __nv_bfloat16* sKh = sQl + 64 * AP;
    __nv_bfloat16* sKl = sKh + 64 * AP;
    __nv_bfloat16* sVh = sKl + 64 * AP;
    __nv_bfloat16* sVl = sVh + 64 * AP;
    float* sMask = reinterpret_cast<float*>(sVl + 64 * AP);

    const int tid = threadIdx.x;
    const int w = tid >> 5, lane = tid & 31;
    const int q0 = blockIdx.x * 64;
    const int h = blockIdx.y, b = blockIdx.z;
    const size_t headbase = (size_t)(b * H_ + h) * LK_ * HD_;
    const size_t qbase = headbase + (size_t)q0 * HD_;

#pragma unroll
    for (int it = 0; it < 4; it++) {
        int idx = tid + it * 128;
        int r = idx >> 3, c = (idx & 7) * 8;
        *reinterpret_cast<uint4*>(&sQh[r * AP + c]) =
            *reinterpret_cast<const uint4*>(&Qh[qbase + (size_t)r * HD_ + c]);
        *reinterpret_cast<uint4*>(&sQl[r * AP + c]) =
            *reinterpret_cast<const uint4*>(&Ql[qbase + (size_t)r * HD_ + c]);
    }
    __syncthreads();

    unsigned qh[4][4], ql[4][4];
    {
        int row = w * 16 + (lane & 15);
#pragma unroll
        for (int kk = 0; kk < 4; kk++) {
            int col = kk * 16 + (lane >> 4) * 8;
            ldsm_x4(qh[kk], smaddr(&sQh[row * AP + col]));
            ldsm_x4(ql[kk], smaddr(&sQl[row * AP + col]));
        }
    }

    float m0 = -3.0e38f, m1 = -3.0e38f, l0 = 0.0f, l1 = 0.0f;
    float Oacc[8][4];
#pragma unroll
    for (int nt = 0; nt < 8; nt++)
#pragma unroll
        for (int r = 0; r < 4; r++) Oacc[nt][r] = 0.0f;

    const int t = lane & 3;

    for (int k0 = 0; k0 < LK_; k0 += 64) {
        __syncthreads();
#pragma unroll
        for (int it = 0; it < 4; it++) {
            int idx = tid + it * 128;
            int r = idx >> 3, c = (idx & 7) * 8;
            size_t g = headbase + (size_t)(k0 + r) * HD_ + c;
            *reinterpret_cast<uint4*>(&sKh[r * AP + c]) =
                *reinterpret_cast<const uint4*>(&Kh[g]);
            *reinterpret_cast<uint4*>(&sKl[r * AP + c]) =
                *reinterpret_cast<const uint4*>(&Kl[g]);
            *reinterpret_cast<uint4*>(&sVh[r * AP + c]) =
                *reinterpret_cast<const uint4*>(&Vh[g]);
            *reinterpret_cast<uint4*>(&sVl[r * AP + c]) =
                *reinterpret_cast<const uint4*>(&Vl[g]);
        }
        if (tid < 64)
            sMask[tid] = mask[b * LK_ + k0 + tid] ? -1.0e30f : 0.0f;
        __syncthreads();

        float S[8][4];
#pragma unroll
        for (int nt = 0; nt < 8; nt++)
#pragma unroll
            for (int r = 0; r < 4; r++) S[nt][r] = 0.0f;

#pragma unroll
        for (int p = 0; p < 4; p++) {
#pragma unroll
            for (int kk = 0; kk < 4; kk++) {
                unsigned kbh[4], kbl[4];
                int row = p * 16 + ((lane >> 4) & 1) * 8 + (lane & 7);
                int col = kk * 16 + ((lane >> 3) & 1) * 8;
                ldsm_x4(kbh, smaddr(&sKh[row * AP + col]));
                ldsm_x4(kbl, smaddr(&sKl[row * AP + col]));
#pragma unroll
                for (int sub = 0; sub < 2; sub++) {
                    unsigned bh2[2] = {kbh[sub * 2], kbh[sub * 2 + 1]};
                    unsigned bl2[2] = {kbl[sub * 2], kbl[sub * 2 + 1]};
                    mma_bf16(S[2 * p + sub], qh[kk], bh2);
                    mma_bf16(S[2 * p + sub], qh[kk], bl2);
                    mma_bf16(S[2 * p + sub], ql[kk], bh2);
                }
            }
        }

        float rmax0 = -3.0e38f, rmax1 = -3.0e38f;
#pragma unroll
        for (int nt = 0; nt < 8; nt++) {
            float mv0 = sMask[nt * 8 + t * 2];
            float mv1 = sMask[nt * 8 + t * 2 + 1];
            S[nt][0] = S[nt][0] * 0.125f + mv0;
            S[nt][1] = S[nt][1] * 0.125f + mv1;
            S[nt][2] = S[nt][2] * 0.125f + mv0;
            S[nt][3] = S[nt][3] * 0.125f + mv1;
            rmax0 = fmaxf(rmax0, fmaxf(S[nt][0], S[nt][1]));
            rmax1 = fmaxf(rmax1, fmaxf(S[nt][2], S[nt][3]));
        }
        rmax0 = fmaxf(rmax0, __shfl_xor_sync(0xffffffffu, rmax0, 1));
        rmax0 = fmaxf(rmax0, __shfl_xor_sync(0xffffffffu, rmax0, 2));
        rmax1 = fmaxf(rmax1, __shfl_xor_sync(0xffffffffu, rmax1, 1));
        rmax1 = fmaxf(rmax1, __shfl_xor_sync(0xffffffffu, rmax1, 2));

        float mn0 = fmaxf(m0, rmax0), mn1 = fmaxf(m1, rmax1);
        float a0 = __expf(m0 - mn0), a1 = __expf(m1 - mn1);
        m0 = mn0; m1 = mn1;

        float rs0 = 0.0f, rs1 = 0.0f;
#pragma unroll
        for (int nt = 0; nt < 8; nt++) {
            S[nt][0] = __expf(S[nt][0] - m0);
            S[nt][1] = __expf(S[nt][1] - m0);
            S[nt][2] = __expf(S[nt][2] - m1);
            S[nt][3] = __expf(S[nt][3] - m1);
            rs0 += S[nt][0] + S[nt][1];
            rs1 += S[nt][2] + S[nt][3];
        }
        rs0 += __shfl_xor_sync(0xffffffffu, rs0, 1);
        rs0 += __shfl_xor_sync(0xffffffffu, rs0, 2);
        rs1 += __shfl_xor_sync(0xffffffffu, rs1, 1);
        rs1 += __shfl_xor_sync(0xffffffffu, rs1, 2);
        l0 = l0 * a0 + rs0;
        l1 = l1 * a1 + rs1;
#pragma unroll
        for (int nt = 0; nt < 8; nt++) {
            Oacc[nt][0] *= a0; Oacc[nt][1] *= a0;
            Oacc[nt][2] *= a1; Oacc[nt][3] *= a1;
        }

#pragma unroll
        for (int j = 0; j < 4; j++) {
            unsigned ah4[4], al4[4];
#pragma unroll
            for (int s2 = 0; s2 < 2; s2++) {
                int nt = 2 * j + s2;
                float p0 = S[nt][0], p1 = S[nt][1];
                float p2 = S[nt][2], p3 = S[nt][3];
                __nv_bfloat162 h01 = __floats2bfloat162_rn(p0, p1);
                __nv_bfloat162 h23 = __floats2bfloat162_rn(p2, p3);
                __nv_bfloat162 l01 = __floats2bfloat162_rn(
                    p0 - __bfloat162float(h01.x), p1 - __bfloat162float(h01.y));
                __nv_bfloat162 l23 = __floats2bfloat162_rn(
                    p2 - __bfloat162float(h23.x), p3 - __bfloat162float(h23.y));
                ah4[s2 * 2]     = *reinterpret_cast<unsigned*>(&h01);
                ah4[s2 * 2 + 1] = *reinterpret_cast<unsigned*>(&h23);
                al4[s2 * 2]     = *reinterpret_cast<unsigned*>(&l01);
                al4[s2 * 2 + 1] = *reinterpret_cast<unsigned*>(&l23);
            }
#pragma unroll
            for (int q = 0; q < 4; q++) {
                unsigned vbh[4], vbl[4];
                int row = j * 16 + ((lane >> 3) & 1) * 8 + (lane & 7);
                int col = q * 16 + ((lane >> 4) & 1) * 8;
                ldsm_x4_t(vbh, smaddr(&sVh[row * AP + col]));
                ldsm_x4_t(vbl, smaddr(&sVl[row * AP + col]));
#pragma unroll
                for (int sub = 0; sub < 2; sub++) {
                    unsigned bh2[2] = {vbh[sub * 2], vbh[sub * 2 + 1]};
                    unsigned bl2[2] = {vbl[sub * 2], vbl[sub * 2 + 1]};
                    mma_bf16(Oacc[2 * q + sub], ah4, bh2);
                    mma_bf16(Oacc[2 * q + sub], ah4, bl2);
                    mma_bf16(Oacc[2 * q + sub], al4, bh2);
                }
            }
        }
    }

    float inv0 = 1.0f / l0, inv1 = 1.0f / l1;
    const int g = lane >> 2;
    int row0 = q0 + w * 16 + g;
#pragma unroll
    for (int nt = 0; nt < 8; nt++) {
        int col = h * HD_ + nt * 8 + t * 2;
        *reinterpret_cast<float2*>(
            &O[((size_t)(b * LQ_) + row0) * D_ + col]) =
            make_float2(Oacc[nt][0] * inv0, Oacc[nt][1] * inv0);
        *reinterpret_cast<float2*>(
            &O[((size_t)(b * LQ_) + row0 + 8) * D_ + col]) =
            make_float2(Oacc[nt][2] * inv1, Oacc[nt][3] * inv1);
    }
}

// ---------------------------------------------------------------------------
extern "C" void kernel_launch(void* const* d_in, const int* in_sizes, int n_in,
                              void* d_out, int out_size)
{
    const float* query = (const float*)d_in[0];
    const float* key   = (const float*)d_in[1];
    const float* value = (const float*)d_in[2];
    const float* Wq = (const float*)d_in[3];
    const float* bq = (const float*)d_in[4];
    const float* Wk = (const float*)d_in[5];
    const float* bk = (const float*)d_in[6];
    const float* Wv = (const float*)d_in[7];
    const float* bv = (const float*)d_in[8];
    const float* Wg = (const float*)d_in[9];
    const float* bg = (const float*)d_in[10];
    const float* Wo = (const float*)d_in[11];
    const float* bo = (const float*)d_in[12];
    const float* rc = (const float*)d_in[13];
    const float* rs = (const float*)d_in[14];
    const unsigned char* mask = (const unsigned char*)d_in[15];
    float* out = (float*)d_out;

    float *Qb, *Kb, *Vb, *Gb, *Ob;
    int8_t *A8h, *A8l, *W8h, *W8l;
    float *SA, *SW;
    __nv_bfloat16 *Qhh, *Qll, *Khh, *Kll, *Vhh, *Vll;
    cudaGetSymbolAddress((void**)&Qb, g_Q);
    cudaGetSymbolAddress((void**)&Kb, g_K);
    cudaGetSymbolAddress((void**)&Vb, g_V);
    cudaGetSymbolAddress((void**)&Gb, g_G);
    cudaGetSymbolAddress((void**)&Ob, g_O);
    cudaGetSymbolAddress((void**)&A8h, g_A8h);
    cudaGetSymbolAddress((void**)&A8l, g_A8l);
    cudaGetSymbolAddress((void**)&W8h, g_W8h);
    cudaGetSymbolAddress((void**)&W8l, g_W8l);
    cudaGetSymbolAddress((void**)&SA, g_SA);
    cudaGetSymbolAddress((void**)&SW, g_SW);
    cudaGetSymbolAddress((void**)&Qhh, g_Qh);
    cudaGetSymbolAddress((void**)&Qll, g_Ql);
    cudaGetSymbolAddress((void**)&Khh, g_Kh);
    cudaGetSymbolAddress((void**)&Kll, g_Kl);
    cudaGetSymbolAddress((void**)&Vhh, g_Vh);
    cudaGetSymbolAddress((void**)&Vll, g_Vl);

    cudaFuncSetAttribute(gemm_s8_kernel,
                         cudaFuncAttributeMaxDynamicSharedMemorySize, QSMEM);
    cudaFuncSetAttribute(attn_mma_kernel,
                         cudaFuncAttributeMaxDynamicSharedMemorySize, ATTN_SMEM);

    dim3 ggrid(D_ / 128, NTOK / 128);   // (8, 64)

    // Quantize all weights and activations up front
    quant_w_all_kernel<<<5 * 1024, 256>>>(Wq, Wg, Wk, Wv, Wo, W8h, W8l, SW);
    quant_act3_kernel<<<3 * 8192, 256>>>(query, key, value, A8h, A8l, SA);

    // 4 projections back-to-back (act slots 0=q,1=k,2=v; w slots 0=Wq,1=Wg,2=Wk,3=Wv,4=Wo)
    gemm_s8_kernel<<<ggrid, 256, QSMEM>>>(
        A8h, A8l, W8h, W8l, SA, SW, bq, Qb, 0);
    gemm_s8_kernel<<<ggrid, 256, QSMEM>>>(
        A8h, A8l, W8h + (size_t)1 * NW, W8l + (size_t)1 * NW,
        SA, SW + 1 * D_, bg, Gb, 1);
    gemm_s8_kernel<<<ggrid, 256, QSMEM>>>(
        A8h + NELEM, A8l + NELEM, W8h + (size_t)2 * NW, W8l + (size_t)2 * NW,
        SA + NTOK, SW + 2 * D_, bk, Kb, 0);
    gemm_s8_kernel<<<ggrid, 256, QSMEM>>>(
        A8h + 2 * NELEM, A8l + 2 * NELEM, W8h + (size_t)3 * NW, W8l + (size_t)3 * NW,
        SA + 2 * NTOK, SW + 3 * D_, bv, Vb, 0);

    // RoPE+split+transpose for Q,K (one launch) and V
    qk_prep2_kernel<<<dim3(B_ * LK_, 2), 256>>>(Qb, Kb, rc, rs, Qhh, Qll, Khh, Kll);
    v_prep_kernel<<<B_ * LK_, 256>>>(Vb, Vhh, Vll);

    // Tensor-core attention (bf16x3)
    attn_mma_kernel<<<dim3(LQ_ / 64, H_, B_), 128, ATTN_SMEM>>>(
        Qhh, Qll, Khh, Kll, Vhh, Vll, mask, Ob);

    // Gate-multiply + quantize into act slot 0, then output projection
    quant_gate_kernel<<<NTOK, 256>>>(Ob, Gb, A8h, A8l, SA);
    gemm_s8_kernel<<<ggrid, 256, QSMEM>>>(
        A8h, A8l, W8h + (size_t)4 * NW, W8l + (size_t)4 * NW,
        SA, SW + 4 * D_, bo, out, 0);
}

// round 17
// speedup vs baseline: 2.2175x; 2.2175x over previous
#include <cuda_runtime.h>
#include <cuda_bf16.h>
#include <math.h>

#define B_  8
#define LQ_ 1024
#define LK_ 1024
#define D_  1024
#define H_  16
#define HD_ 64
#define NTOK (B_ * LQ_)
#define NELEM ((size_t)B_ * LQ_ * D_)
#define NW (D_ * D_)

// Scratch (static device globals)
__device__ float g_Q[NELEM];
__device__ float g_K[NELEM];
__device__ float g_V[NELEM];
__device__ float g_G[NELEM];
__device__ float g_O[NELEM];
// activation splits: slot 0=query(->gateO reuse), 1=key, 2=value
__device__ __nv_bfloat16 g_Xh[3 * NELEM];
__device__ __nv_bfloat16 g_Xl[3 * NELEM];
// weight splits: slots 0..4 = Wq, Wg, Wk, Wv, Wo
__device__ __nv_bfloat16 g_Wh5[5 * NW];
__device__ __nv_bfloat16 g_Wl5[5 * NW];
// head-major [B,H,L,HD] bf16 hi/lo for attention
__device__ __nv_bfloat16 g_Qh[NELEM];
__device__ __nv_bfloat16 g_Ql[NELEM];
__device__ __nv_bfloat16 g_Kh[NELEM];
__device__ __nv_bfloat16 g_Kl[NELEM];
__device__ __nv_bfloat16 g_Vh[NELEM];
__device__ __nv_bfloat16 g_Vl[NELEM];

// ---------------------------------------------------------------------------
// PTX helpers
// ---------------------------------------------------------------------------
__device__ __forceinline__ void ldsm_x4(unsigned* r, unsigned addr) {
    asm volatile("ldmatrix.sync.aligned.m8n8.x4.shared.b16 {%0,%1,%2,%3}, [%4];\n"
                 : "=r"(r[0]), "=r"(r[1]), "=r"(r[2]), "=r"(r[3]) : "r"(addr));
}
__device__ __forceinline__ void ldsm_x4_t(unsigned* r, unsigned addr) {
    asm volatile("ldmatrix.sync.aligned.m8n8.x4.trans.shared.b16 {%0,%1,%2,%3}, [%4];\n"
                 : "=r"(r[0]), "=r"(r[1]), "=r"(r[2]), "=r"(r[3]) : "r"(addr));
}
__device__ __forceinline__ void mma_bf16(float* c, const unsigned* a, const unsigned* b) {
    asm volatile(
        "mma.sync.aligned.m16n8k16.row.col.f32.bf16.bf16.f32 "
        "{%0,%1,%2,%3}, {%4,%5,%6,%7}, {%8,%9}, {%0,%1,%2,%3};\n"
        : "+f"(c[0]), "+f"(c[1]), "+f"(c[2]), "+f"(c[3])
        : "r"(a[0]), "r"(a[1]), "r"(a[2]), "r"(a[3]), "r"(b[0]), "r"(b[1]));
}
__device__ __forceinline__ unsigned smaddr(const void* p) {
    return (unsigned)__cvta_generic_to_shared(p);
}
__device__ __forceinline__ void cp_async16(unsigned dst, const void* src) {
    asm volatile("cp.async.cg.shared.global [%0], [%1], 16;\n"
                 :: "r"(dst), "l"(src));
}
__device__ __forceinline__ void cp_commit() {
    asm volatile("cp.async.commit_group;\n");
}
template <int N>
__device__ __forceinline__ void cp_wait() {
    asm volatile("cp.async.wait_group %0;\n" :: "n"(N));
}

// ---------------------------------------------------------------------------
// Split helpers
// ---------------------------------------------------------------------------
__device__ __forceinline__ void split4(const float* src, __nv_bfloat16* hi,
                                       __nv_bfloat16* lo, size_t i)
{
    float4 v = *reinterpret_cast<const float4*>(src + i);
    float vv[4] = {v.x, v.y, v.z, v.w};
    __nv_bfloat16 h[4], l[4];
#pragma unroll
    for (int j = 0; j < 4; j++) {
        h[j] = __float2bfloat16_rn(vv[j]);
        l[j] = __float2bfloat16_rn(vv[j] - __bfloat162float(h[j]));
    }
    *reinterpret_cast<uint2*>(hi + i) = *reinterpret_cast<uint2*>(h);
    *reinterpret_cast<uint2*>(lo + i) = *reinterpret_cast<uint2*>(l);
}

__global__ void split_w_all_kernel(const float* __restrict__ W0,
                                   const float* __restrict__ W1,
                                   const float* __restrict__ W2,
                                   const float* __restrict__ W3,
                                   const float* __restrict__ W4,
                                   __nv_bfloat16* __restrict__ hi,
                                   __nv_bfloat16* __restrict__ lo)
{
    int m = blockIdx.x >> 10;
    int blk = blockIdx.x & 1023;
    size_t i = ((size_t)blk * 256 + threadIdx.x) * 4;
    const float* W = (m == 0) ? W0 : (m == 1) ? W1 : (m == 2) ? W2
                   : (m == 3) ? W3 : W4;
    split4(W, hi + (size_t)m * NW, lo + (size_t)m * NW, i);
}

__global__ void split_act3_kernel(const float* __restrict__ X0,
                                  const float* __restrict__ X1,
                                  const float* __restrict__ X2,
                                  __nv_bfloat16* __restrict__ hi,
                                  __nv_bfloat16* __restrict__ lo)
{
    int m = blockIdx.x >> 13;
    int blk = blockIdx.x & 8191;
    size_t i = ((size_t)blk * 256 + threadIdx.x) * 4;
    const float* X = (m == 0) ? X0 : (m == 1) ? X1 : X2;
    split4(X, hi + (size_t)m * NELEM, lo + (size_t)m * NELEM, i);
}

__global__ void gate_split_kernel(const float* __restrict__ O,
                                  const float* __restrict__ G,
                                  __nv_bfloat16* __restrict__ hi,
                                  __nv_bfloat16* __restrict__ lo, int n)
{
    int i = (blockIdx.x * blockDim.x + threadIdx.x) * 4;
    if (i >= n) return;
    float4 o = *reinterpret_cast<const float4*>(O + i);
    float4 g = *reinterpret_cast<const float4*>(G + i);
    float vv[4] = {o.x * g.x, o.y * g.y, o.z * g.z, o.w * g.w};
    __nv_bfloat16 h[4], l[4];
#pragma unroll
    for (int j = 0; j < 4; j++) {
        h[j] = __float2bfloat16_rn(vv[j]);
        l[j] = __float2bfloat16_rn(vv[j] - __bfloat162float(h[j]));
    }
    *reinterpret_cast<uint2*>(hi + i) = *reinterpret_cast<uint2*>(h);
    *reinterpret_cast<uint2*>(lo + i) = *reinterpret_cast<uint2*>(l);
}

// ---------------------------------------------------------------------------
// Batched bf16x3 GEMM: blockIdx.z selects (activation slot, weight slot,
// bias, output, act-flag). Same body as R15 (single-sync 2-stage pipeline).
// ---------------------------------------------------------------------------
#define PBM 128
#define PBN 128
#define PBK 32
#define PLDA 40
#define PSTAGE (PBM * PLDA)
#define GEMM_SMEM (2 * 4 * PSTAGE * 2)      // 81920 B

struct GemmBatch {
    const __nv_bfloat16 *Ah[4], *Al[4], *Wh[4], *Wl[4];
    const float* bias[4];
    float* C[4];
    int act[4];
};

__device__ __forceinline__ void gemm_body(
    const __nv_bfloat16* __restrict__ Ah, const __nv_bfloat16* __restrict__ Al,
    const __nv_bfloat16* __restrict__ Wh, const __nv_bfloat16* __restrict__ Wl,
    const float* __restrict__ bias, float* __restrict__ C, int act,
    __nv_bfloat16* sm)
{
    const int tid = threadIdx.x;
    const int wid = tid >> 5, lane = tid & 31;
    const int bm = blockIdx.y * PBM, bn = blockIdx.x * PBN;
    const int wm = (wid >> 2) * 64, wn = (wid & 3) * 32;

    const int cr = tid >> 1;
    const int cc = (tid & 1) * 16;

    float acc[4][4][4];
#pragma unroll
    for (int a = 0; a < 4; a++)
#pragma unroll
        for (int b = 0; b < 4; b++)
#pragma unroll
            for (int c = 0; c < 4; c++) acc[a][b][c] = 0.0f;

    auto copy_stage = [&](int s, int kb) {
        __nv_bfloat16* base = sm + (size_t)s * 4 * PSTAGE;
        const int kc = kb * PBK + cc;
        unsigned d = smaddr(&base[cr * PLDA + cc]);
        const size_t ga = (size_t)(bm + cr) * 1024 + kc;
        const size_t gw = (size_t)(bn + cr) * 1024 + kc;
        cp_async16(d,                          &Ah[ga]);
        cp_async16(d + 16,                     &Ah[ga + 8]);
        cp_async16(d + 1 * PSTAGE * 2,         &Al[ga]);
        cp_async16(d + 1 * PSTAGE * 2 + 16,    &Al[ga + 8]);
        cp_async16(d + 2 * PSTAGE * 2,         &Wh[gw]);
        cp_async16(d + 2 * PSTAGE * 2 + 16,    &Wh[gw + 8]);
        cp_async16(d + 3 * PSTAGE * 2,         &Wl[gw]);
        cp_async16(d + 3 * PSTAGE * 2 + 16,    &Wl[gw + 8]);
    };

    copy_stage(0, 0);
    cp_commit();

    const int NKB = 1024 / PBK;
    for (int kb = 0; kb < NKB; kb++) {
        cp_wait<0>();
        __syncthreads();
        if (kb + 1 < NKB) {
            copy_stage((kb + 1) & 1, kb + 1);
            cp_commit();
        }

        {
            const __nv_bfloat16* bAh = sm + (size_t)(kb & 1) * 4 * PSTAGE;
            const __nv_bfloat16* bAl = bAh + PSTAGE;
            const __nv_bfloat16* bWh = bAl + PSTAGE;
            const __nv_bfloat16* bWl = bWh + PSTAGE;
#pragma unroll
            for (int kk = 0; kk < PBK; kk += 16) {
                unsigned ah[4][4], al[4][4], bh[2][4], bl[2][4];
#pragma unroll
                for (int mt = 0; mt < 4; mt++) {
                    int row = wm + mt * 16 + (lane & 15);
                    int col = kk + (lane >> 4) * 8;
                    ldsm_x4(ah[mt], smaddr(&bAh[row * PLDA + col]));
                    ldsm_x4(al[mt], smaddr(&bAl[row * PLDA + col]));
                }
#pragma unroll
                for (int p = 0; p < 2; p++) {
                    int row = wn + p * 16 + ((lane >> 4) & 1) * 8 + (lane & 7);
                    int col = kk + ((lane >> 3) & 1) * 8;
                    ldsm_x4(bh[p], smaddr(&bWh[row * PLDA + col]));
                    ldsm_x4(bl[p], smaddr(&bWl[row * PLDA + col]));
                }
#pragma unroll
                for (int mt = 0; mt < 4; mt++) {
#pragma unroll
                    for (int nt = 0; nt < 4; nt++) {
                        unsigned bhf[2] = { bh[nt >> 1][(nt & 1) * 2],
                                            bh[nt >> 1][(nt & 1) * 2 + 1] };
                        unsigned blf[2] = { bl[nt >> 1][(nt & 1) * 2],
                                            bl[nt >> 1][(nt & 1) * 2 + 1] };
                        mma_bf16(acc[mt][nt], ah[mt], bhf);
                        mma_bf16(acc[mt][nt], ah[mt], blf);
                        mma_bf16(acc[mt][nt], al[mt], bhf);
                    }
                }
            }
        }
    }

    const int g = lane >> 2, t = lane & 3;
#pragma unroll
    for (int mt = 0; mt < 4; mt++) {
#pragma unroll
        for (int nt = 0; nt < 4; nt++) {
            int row = bm + wm + mt * 16 + g;
            int col = bn + wn + nt * 8 + t * 2;
            float b0 = bias[col], b1 = bias[col + 1];
            float c0 = acc[mt][nt][0] + b0;
            float c1 = acc[mt][nt][1] + b1;
            float c2 = acc[mt][nt][2] + b0;
            float c3 = acc[mt][nt][3] + b1;
            if (act) {
                c0 = 1.0f / (1.0f + __expf(-c0));
                c1 = 1.0f / (1.0f + __expf(-c1));
                c2 = 1.0f / (1.0f + __expf(-c2));
                c3 = 1.0f / (1.0f + __expf(-c3));
            }
            *reinterpret_cast<float2*>(&C[(size_t)row * 1024 + col]) = make_float2(c0, c1);
            *reinterpret_cast<float2*>(&C[(size_t)(row + 8) * 1024 + col]) = make_float2(c2, c3);
        }
    }
}

__global__ __launch_bounds__(256, 2) void gemm_batch4_kernel(GemmBatch gb)
{
    extern __shared__ __nv_bfloat16 sm[];
    int z = blockIdx.z;
    gemm_body(gb.Ah[z], gb.Al[z], gb.Wh[z], gb.Wl[z],
              gb.bias[z], gb.C[z], gb.act[z], sm);
}

__global__ __launch_bounds__(256, 2) void gemm_single_kernel(
    const __nv_bfloat16* __restrict__ Ah, const __nv_bfloat16* __restrict__ Al,
    const __nv_bfloat16* __restrict__ Wh, const __nv_bfloat16* __restrict__ Wl,
    const float* __restrict__ bias, float* __restrict__ C, int act)
{
    extern __shared__ __nv_bfloat16 sm[];
    gemm_body(Ah, Al, Wh, Wl, bias, C, act, sm);
}

// ---------------------------------------------------------------------------
// Merged prep: blockIdx.y: 0=Q rope, 1=K rope, 2=V split. All to head-major.
// ---------------------------------------------------------------------------
__global__ void prep3_kernel(const float* __restrict__ Qsrc,
                             const float* __restrict__ Ksrc,
                             const float* __restrict__ Vsrc,
                             const float* __restrict__ cosb,
                             const float* __restrict__ sinb,
                             __nv_bfloat16* __restrict__ Qhi,
                             __nv_bfloat16* __restrict__ Qlo,
                             __nv_bfloat16* __restrict__ Khi,
                             __nv_bfloat16* __restrict__ Klo,
                             __nv_bfloat16* __restrict__ Vhi,
                             __nv_bfloat16* __restrict__ Vlo)
{
    int which = blockIdx.y;
    int bl = blockIdx.x;
    int b = bl >> 10, l = bl & 1023;
    int h = threadIdx.x >> 4, j = threadIdx.x & 15;

    if (which == 2) {
        int d0 = j * 4;
        size_t ibase = (size_t)bl * D_ + h * HD_ + d0;
        size_t obase = ((size_t)(b * H_ + h) * LK_ + l) * HD_ + d0;
        float4 v = *reinterpret_cast<const float4*>(&Vsrc[ibase]);
        float vv[4] = {v.x, v.y, v.z, v.w};
        __nv_bfloat16 hh[4], ll[4];
#pragma unroll
        for (int i = 0; i < 4; i++) {
            hh[i] = __float2bfloat16_rn(vv[i]);
            ll[i] = __float2bfloat16_rn(vv[i] - __bfloat162float(hh[i]));
        }
        *reinterpret_cast<uint2*>(&Vhi[obase]) = *reinterpret_cast<uint2*>(hh);
        *reinterpret_cast<uint2*>(&Vlo[obase]) = *reinterpret_cast<uint2*>(ll);
        return;
    }

    const float* X = which ? Ksrc : Qsrc;
    __nv_bfloat16* hi = which ? Khi : Qhi;
    __nv_bfloat16* lo = which ? Klo : Qlo;
    int d0 = j * 2;

    size_t ibase = (size_t)bl * D_ + h * HD_;
    size_t obase = ((size_t)(b * H_ + h) * LK_ + l) * HD_;
    size_t cbase = (size_t)bl * HD_;

    float x0 = X[ibase + d0],      x1 = X[ibase + d0 + 1];
    float y0 = X[ibase + d0 + 32], y1 = X[ibase + d0 + 33];
    float cA0 = cosb[cbase + d0],      sA0 = sinb[cbase + d0];
    float cA1 = cosb[cbase + d0 + 1],  sA1 = sinb[cbase + d0 + 1];
    float cB0 = cosb[cbase + d0 + 32], sB0 = sinb[cbase + d0 + 32];
    float cB1 = cosb[cbase + d0 + 33], sB1 = sinb[cbase + d0 + 33];

    float r0 = x0 * cA0 - y0 * sA0;
    float r1 = x1 * cA1 - y1 * sA1;
    float r2 = y0 * cB0 + x0 * sB0;
    float r3 = y1 * cB1 + x1 * sB1;

    __nv_bfloat16 h0 = __float2bfloat16_rn(r0), h1 = __float2bfloat16_rn(r1);
    __nv_bfloat16 h2 = __float2bfloat16_rn(r2), h3 = __float2bfloat16_rn(r3);
    __nv_bfloat162 hp0; hp0.x = h0; hp0.y = h1;
    __nv_bfloat162 hp1; hp1.x = h2; hp1.y = h3;
    __nv_bfloat162 lp0;
    lp0.x = __float2bfloat16_rn(r0 - __bfloat162float(h0));
    lp0.y = __float2bfloat16_rn(r1 - __bfloat162float(h1));
    __nv_bfloat162 lp1;
    lp1.x = __float2bfloat16_rn(r2 - __bfloat162float(h2));
    lp1.y = __float2bfloat16_rn(r3 - __bfloat162float(h3));

    *reinterpret_cast<__nv_bfloat162*>(&hi[obase + d0]) = hp0;
    *reinterpret_cast<__nv_bfloat162*>(&hi[obase + d0 + 32]) = hp1;
    *reinterpret_cast<__nv_bfloat162*>(&lo[obase + d0]) = lp0;
    *reinterpret_cast<__nv_bfloat162*>(&lo[obase + d0 + 32]) = lp1;
}

// ---------------------------------------------------------------------------
// Tensor-core flash attention (bf16x3), unchanged (passing since R5).
// ---------------------------------------------------------------------------
#define AP 72
#define ATTN_SMEM (6 * 64 * AP * 2 + 64 * 4)

__global__ __launch_bounds__(128) void attn_mma_kernel(
    const __nv_bfloat16* __restrict__ Qh, const __nv_bfloat16* __restrict__ Ql,
    const __nv_bfloat16* __restrict__ Kh, const __nv_bfloat16* __restrict__ Kl,
    const __nv_bfloat16* __restrict__ Vh, const __nv_bfloat16* __restrict__ Vl,
    const unsigned char* __restrict__ mask, float* __restrict__ O)
{
    extern __shared__ char smraw[];
    __nv_bfloat16* sQh = reinterpret_cast<__nv_bfloat16*>(smraw);
    __nv_bfloat16* sQl = sQh + 64 * AP;
    __nv_bfloat16* sKh = sQl + 64 * AP;
    __nv_bfloat16* sKl = sKh + 64 * AP;
    __nv_bfloat16* sVh = sKl + 64 * AP;
    __nv_bfloat16* sVl = sVh + 64 * AP;
    float* sMask = reinterpret_cast<float*>(sVl + 64 * AP);

    const int tid = threadIdx.x;
    const int w = tid >> 5, lane = tid & 31;
    const int q0 = blockIdx.x * 64;
    const int h = blockIdx.y, b = blockIdx.z;
    const size_t headbase = (size_t)(b * H_ + h) * LK_ * HD_;
    const size_t qbase = headbase + (size_t)q0 * HD_;

#pragma unroll
    for (int it = 0; it < 4; it++) {
        int idx = tid + it * 128;
        int r = idx >> 3, c = (idx & 7) * 8;
        *reinterpret_cast<uint4*>(&sQh[r * AP + c]) =
            *reinterpret_cast<const uint4*>(&Qh[qbase + (size_t)r * HD_ + c]);
        *reinterpret_cast<uint4*>(&sQl[r * AP + c]) =
            *reinterpret_cast<const uint4*>(&Ql[qbase + (size_t)r * HD_ + c]);
    }
    __syncthreads();

    unsigned qh[4][4], ql[4][4];
    {
        int row = w * 16 + (lane & 15);
#pragma unroll
        for (int kk = 0; kk < 4; kk++) {
            int col = kk * 16 + (lane >> 4) * 8;
            ldsm_x4(qh[kk], smaddr(&sQh[row * AP + col]));
            ldsm_x4(ql[kk], smaddr(&sQl[row * AP + col]));
        }
    }

    float m0 = -3.0e38f, m1 = -3.0e38f, l0 = 0.0f, l1 = 0.0f;
    float Oacc[8][4];
#pragma unroll
    for (int nt = 0; nt < 8; nt++)
#pragma unroll
        for (int r = 0; r < 4; r++) Oacc[nt][r] = 0.0f;

    const int t = lane & 3;

    for (int k0 = 0; k0 < LK_; k0 += 64) {
        __syncthreads();
#pragma unroll
        for (int it = 0; it < 4; it++) {
            int idx = tid + it * 128;
            int r = idx >> 3, c = (idx & 7) * 8;
            size_t g = headbase + (size_t)(k0 + r) * HD_ + c;
            *reinterpret_cast<uint4*>(&sKh[r * AP + c]) =
                *reinterpret_cast<const uint4*>(&Kh[g]);
            *reinterpret_cast<uint4*>(&sKl[r * AP + c]) =
                *reinterpret_cast<const uint4*>(&Kl[g]);
            *reinterpret_cast<uint4*>(&sVh[r * AP + c]) =
                *reinterpret_cast<const uint4*>(&Vh[g]);
            *reinterpret_cast<uint4*>(&sVl[r * AP + c]) =
                *reinterpret_cast<const uint4*>(&Vl[g]);
        }
        if (tid < 64)
            sMask[tid] = mask[b * LK_ + k0 + tid] ? -1.0e30f : 0.0f;
        __syncthreads();

        float S[8][4];
#pragma unroll
        for (int nt = 0; nt < 8; nt++)
#pragma unroll
            for (int r = 0; r < 4; r++) S[nt][r] = 0.0f;

#pragma unroll
        for (int p = 0; p < 4; p++) {
#pragma unroll
            for (int kk = 0; kk < 4; kk++) {
                unsigned kbh[4], kbl[4];
                int row = p * 16 + ((lane >> 4) & 1) * 8 + (lane & 7);
                int col = kk * 16 + ((lane >> 3) & 1) * 8;
                ldsm_x4(kbh, smaddr(&sKh[row * AP + col]));
                ldsm_x4(kbl, smaddr(&sKl[row * AP + col]));
#pragma unroll
                for (int sub = 0; sub < 2; sub++) {
                    unsigned bh2[2] = {kbh[sub * 2], kbh[sub * 2 + 1]};
                    unsigned bl2[2] = {kbl[sub * 2], kbl[sub * 2 + 1]};
                    mma_bf16(S[2 * p + sub], qh[kk], bh2);
                    mma_bf16(S[2 * p + sub], qh[kk], bl2);
                    mma_bf16(S[2 * p + sub], ql[kk], bh2);
                }
            }
        }

        float rmax0 = -3.0e38f, rmax1 = -3.0e38f;
#pragma unroll
        for (int nt = 0; nt < 8; nt++) {
            float mv0 = sMask[nt * 8 + t * 2];
            float mv1 = sMask[nt * 8 + t * 2 + 1];
            S[nt][0] = S[nt][0] * 0.125f + mv0;
            S[nt][1] = S[nt][1] * 0.125f + mv1;
            S[nt][2] = S[nt][2] * 0.125f + mv0;
            S[nt][3] = S[nt][3] * 0.125f + mv1;
            rmax0 = fmaxf(rmax0, fmaxf(S[nt][0], S[nt][1]));
            rmax1 = fmaxf(rmax1, fmaxf(S[nt][2], S[nt][3]));
        }
        rmax0 = fmaxf(rmax0, __shfl_xor_sync(0xffffffffu, rmax0, 1));
        rmax0 = fmaxf(rmax0, __shfl_xor_sync(0xffffffffu, rmax0, 2));
        rmax1 = fmaxf(rmax1, __shfl_xor_sync(0xffffffffu, rmax1, 1));
        rmax1 = fmaxf(rmax1, __shfl_xor_sync(0xffffffffu, rmax1, 2));

        float mn0 = fmaxf(m0, rmax0), mn1 = fmaxf(m1, rmax1);
        float a0 = __expf(m0 - mn0), a1 = __expf(m1 - mn1);
        m0 = mn0; m1 = mn1;

        float rs0 = 0.0f, rs1 = 0.0f;
#pragma unroll
        for (int nt = 0; nt < 8; nt++) {
            S[nt][0] = __expf(S[nt][0] - m0);
            S[nt][1] = __expf(S[nt][1] - m0);
            S[nt][2] = __expf(S[nt][2] - m1);
            S[nt][3] = __expf(S[nt][3] - m1);
            rs0 += S[nt][0] + S[nt][1];
            rs1 += S[nt][2] + S[nt][3];
        }
        rs0 += __shfl_xor_sync(0xffffffffu, rs0, 1);
        rs0 += __shfl_xor_sync(0xffffffffu, rs0, 2);
        rs1 += __shfl_xor_sync(0xffffffffu, rs1, 1);
        rs1 += __shfl_xor_sync(0xffffffffu, rs1, 2);
        l0 = l0 * a0 + rs0;
        l1 = l1 * a1 + rs1;
#pragma unroll
        for (int nt = 0; nt < 8; nt++) {
            Oacc[nt][0] *= a0; Oacc[nt][1] *= a0;
            Oacc[nt][2] *= a1; Oacc[nt][3] *= a1;
        }

#pragma unroll
        for (int j = 0; j < 4; j++) {
            unsigned ah4[4], al4[4];
#pragma unroll
            for (int s2 = 0; s2 < 2; s2++) {
                int nt = 2 * j + s2;
                float p0 = S[nt][0], p1 = S[nt][1];
                float p2 = S[nt][2], p3 = S[nt][3];
                __nv_bfloat162 h01 = __floats2bfloat162_rn(p0, p1);
                __nv_bfloat162 h23 = __floats2bfloat162_rn(p2, p3);
                __nv_bfloat162 l01 = __floats2bfloat162_rn(
                    p0 - __bfloat162float(h01.x), p1 - __bfloat162float(h01.y));
                __nv_bfloat162 l23 = __floats2bfloat162_rn(
                    p2 - __bfloat162float(h23.x), p3 - __bfloat162float(h23.y));
                ah4[s2 * 2]     = *reinterpret_cast<unsigned*>(&h01);
                ah4[s2 * 2 + 1] = *reinterpret_cast<unsigned*>(&h23);
                al4[s2 * 2]     = *reinterpret_cast<unsigned*>(&l01);
                al4[s2 * 2 + 1] = *reinterpret_cast<unsigned*>(&l23);
            }
#pragma unroll
            for (int q = 0; q < 4; q++) {
                unsigned vbh[4], vbl[4];
                int row = j * 16 + ((lane >> 3) & 1) * 8 + (lane & 7);
                int col = q * 16 + ((lane >> 4) & 1) * 8;
                ldsm_x4_t(vbh, smaddr(&sVh[row * AP + col]));
                ldsm_x4_t(vbl, smaddr(&sVl[row * AP + col]));
#pragma unroll
                for (int sub = 0; sub < 2; sub++) {
                    unsigned bh2[2] = {vbh[sub * 2], vbh[sub * 2 + 1]};
                    unsigned bl2[2] = {vbl[sub * 2], vbl[sub * 2 + 1]};
                    mma_bf16(Oacc[2 * q + sub], ah4, bh2);
                    mma_bf16(Oacc[2 * q + sub], ah4, bl2);
                    mma_bf16(Oacc[2 * q + sub], al4, bh2);
                }
            }
        }
    }

    float inv0 = 1.0f / l0, inv1 = 1.0f / l1;
    const int g = lane >> 2;
    int row0 = q0 + w * 16 + g;
#pragma unroll
    for (int nt = 0; nt < 8; nt++) {
        int col = h * HD_ + nt * 8 + t * 2;
        *reinterpret_cast<float2*>(
            &O[((size_t)(b * LQ_) + row0) * D_ + col]) =
            make_float2(Oacc[nt][0] * inv0, Oacc[nt][1] * inv0);
        *reinterpret_cast<float2*>(
            &O[((size_t)(b * LQ_) + row0 + 8) * D_ + col]) =
            make_float2(Oacc[nt][2] * inv1, Oacc[nt][3] * inv1);
    }
}

// ---------------------------------------------------------------------------
extern "C" void kernel_launch(void* const* d_in, const int* in_sizes, int n_in,
                              void* d_out, int out_size)
{
    const float* query = (const float*)d_in[0];
    const float* key   = (const float*)d_in[1];
    const float* value = (const float*)d_in[2];
    const float* Wq = (const float*)d_in[3];
    const float* bq = (const float*)d_in[4];
    const float* Wk = (const float*)d_in[5];
    const float* bk = (const float*)d_in[6];
    const float* Wv = (const float*)d_in[7];
    const float* bv = (const float*)d_in[8];
    const float* Wg = (const float*)d_in[9];
    const float* bg = (const float*)d_in[10];
    const float* Wo = (const float*)d_in[11];
    const float* bo = (const float*)d_in[12];
    const float* rc = (const float*)d_in[13];
    const float* rs = (const float*)d_in[14];
    const unsigned char* mask = (const unsigned char*)d_in[15];
    float* out = (float*)d_out;

    float *Qb, *Kb, *Vb, *Gb, *Ob;
    __nv_bfloat16 *Xh, *Xl, *Wh5, *Wl5;
    __nv_bfloat16 *Qhh, *Qll, *Khh, *Kll, *Vhh, *Vll;
    cudaGetSymbolAddress((void**)&Qb, g_Q);
    cudaGetSymbolAddress((void**)&Kb, g_K);
    cudaGetSymbolAddress((void**)&Vb, g_V);
    cudaGetSymbolAddress((void**)&Gb, g_G);
    cudaGetSymbolAddress((void**)&Ob, g_O);
    cudaGetSymbolAddress((void**)&Xh, g_Xh);
    cudaGetSymbolAddress((void**)&Xl, g_Xl);
    cudaGetSymbolAddress((void**)&Wh5, g_Wh5);
    cudaGetSymbolAddress((void**)&Wl5, g_Wl5);
    cudaGetSymbolAddress((void**)&Qhh, g_Qh);
    cudaGetSymbolAddress((void**)&Qll, g_Ql);
    cudaGetSymbolAddress((void**)&Khh, g_Kh);
    cudaGetSymbolAddress((void**)&Kll, g_Kl);
    cudaGetSymbolAddress((void**)&Vhh, g_Vh);
    cudaGetSymbolAddress((void**)&Vll, g_Vl);

    cudaFuncSetAttribute(gemm_batch4_kernel,
                         cudaFuncAttributeMaxDynamicSharedMemorySize, GEMM_SMEM);
    cudaFuncSetAttribute(gemm_single_kernel,
                         cudaFuncAttributeMaxDynamicSharedMemorySize, GEMM_SMEM);
    cudaFuncSetAttribute(attn_mma_kernel,
                         cudaFuncAttributeMaxDynamicSharedMemorySize, ATTN_SMEM);

    const int na = (int)NELEM;

    // All splits up front (2 launches)
    split_w_all_kernel<<<5 * 1024, 256>>>(Wq, Wg, Wk, Wv, Wo, Wh5, Wl5);
    split_act3_kernel<<<3 * 8192, 256>>>(query, key, value, Xh, Xl);

    // 4 projections in ONE launch (z selects GEMM)
    GemmBatch gb;
    gb.Ah[0] = Xh;             gb.Al[0] = Xl;
    gb.Wh[0] = Wh5;            gb.Wl[0] = Wl5;
    gb.bias[0] = bq; gb.C[0] = Qb; gb.act[0] = 0;
    gb.Ah[1] = Xh;             gb.Al[1] = Xl;
    gb.Wh[1] = Wh5 + (size_t)1 * NW; gb.Wl[1] = Wl5 + (size_t)1 * NW;
    gb.bias[1] = bg; gb.C[1] = Gb; gb.act[1] = 1;
    gb.Ah[2] = Xh + NELEM;     gb.Al[2] = Xl + NELEM;
    gb.Wh[2] = Wh5 + (size_t)2 * NW; gb.Wl[2] = Wl5 + (size_t)2 * NW;
    gb.bias[2] = bk; gb.C[2] = Kb; gb.act[2] = 0;
    gb.Ah[3] = Xh + 2 * NELEM; gb.Al[3] = Xl + 2 * NELEM;
    gb.Wh[3] = Wh5 + (size_t)3 * NW; gb.Wl[3] = Wl5 + (size_t)3 * NW;
    gb.bias[3] = bv; gb.C[3] = Vb; gb.act[3] = 0;
    gemm_batch4_kernel<<<dim3(D_ / PBN, NTOK / PBM, 4), 256, GEMM_SMEM>>>(gb);

    // RoPE/split prep for Q, K, V in one launch
    prep3_kernel<<<dim3(B_ * LK_, 3), 256>>>(
        Qb, Kb, Vb, rc, rs, Qhh, Qll, Khh, Kll, Vhh, Vll);

    // Tensor-core attention
    attn_mma_kernel<<<dim3(LQ_ / 64, H_, B_), 128, ATTN_SMEM>>>(
        Qhh, Qll, Khh, Kll, Vhh, Vll, mask, Ob);

    // Gate-multiply + split into act slot 0, then output projection
    gate_split_kernel<<<na / 1024, 256>>>(Ob, Gb, Xh, Xl, na);
    gemm_single_kernel<<<dim3(D_ / PBN, NTOK / PBM), 256, GEMM_SMEM>>>(
        Xh, Xl, Wh5 + (size_t)4 * NW, Wl5 + (size_t)4 * NW, bo, out, 0);
}